// round 14
// baseline (speedup 1.0000x reference)
#include <cuda_runtime.h>
#include <cuda_fp16.h>
#include <cstdint>

// ---------------- problem dims ----------------
#define M_DIM 4096
#define N_DIM 1024
#define E_DIM 16
#define I_DIM 1024
#define K_DIM 16384

// ---------------- GEMM config -----------------
#define BM 128
#define BN 128
#define BK 64
#define STAGES 3
#define NTHREADS 256
#define KCHUNKS 8               // chunk z = experts {2z, 2z+1} = 32 BK-iters
#define NT_ITERS 32

// smem: 3 stages of (A 16KB + B 16KB), mbarriers, cw-scale table
#define A_OFF 0
#define B_OFF 16384
#define STAGE_BYTES 32768
#define BAR_BASE (STAGES * STAGE_BYTES)          // 98304
#define FULL_OFF(s)  (BAR_BASE + (s) * 8)
#define EMPTY_OFF(s) (BAR_BASE + 24 + (s) * 8)
#define CW_OFF   (BAR_BASE + 64)                 // 2 x 128 half2 = 1KB
#define SMEM_TOTAL (CW_OFF + 1024)               // 99392 -> 2 CTAs/SM

// ---------------- device scratch --------------
__device__ __align__(1024) __half g_X [(size_t)M_DIM * I_DIM];  // 8 MiB:  x fp16
__device__ __align__(1024) __half g_Wt[(size_t)N_DIM * K_DIM];  // 32 MiB: W^T [n][e*1024+i]

// ---------------- prep kernels ----------------
__global__ void prep_x_kernel(const float* __restrict__ x) {
    size_t idx    = (size_t)blockIdx.x * blockDim.x + threadIdx.x;
    size_t stride = (size_t)gridDim.x * blockDim.x;
    const size_t total8 = (size_t)M_DIM * I_DIM / 8;
    for (; idx < total8; idx += stride) {
        size_t base = idx * 8;
        float4 x0 = *reinterpret_cast<const float4*>(x + base);
        float4 x1 = *reinterpret_cast<const float4*>(x + base + 4);
        __half2 h0 = __floats2half2_rn(x0.x, x0.y);
        __half2 h1 = __floats2half2_rn(x0.z, x0.w);
        __half2 h2 = __floats2half2_rn(x1.x, x1.y);
        __half2 h3 = __floats2half2_rn(x1.z, x1.w);
        uint4 o;
        o.x = *reinterpret_cast<uint32_t*>(&h0);
        o.y = *reinterpret_cast<uint32_t*>(&h1);
        o.z = *reinterpret_cast<uint32_t*>(&h2);
        o.w = *reinterpret_cast<uint32_t*>(&h3);
        *reinterpret_cast<uint4*>(g_X + base) = o;
    }
}

// Transpose W[k][o] -> Wt[o][k] fp16 (k = e*1024 + i)
__global__ void prep_w_kernel(const float* __restrict__ W) {
    __shared__ float t[32][33];
    const int k0 = blockIdx.x * 32, o0 = blockIdx.y * 32;
    const int tx = threadIdx.x, ty = threadIdx.y;  // 32 x 8
#pragma unroll
    for (int i = 0; i < 4; ++i)
        t[ty + i * 8][tx] = W[(size_t)(k0 + ty + i * 8) * N_DIM + o0 + tx];
    __syncthreads();
#pragma unroll
    for (int i = 0; i < 4; ++i) {
        float v = t[tx][ty + i * 8];
        g_Wt[(size_t)(o0 + ty + i * 8) * K_DIM + k0 + tx] = __float2half_rn(v);
    }
}

// out = cw @ bias  (atomics accumulate the GEMM partials on top)
__global__ void init_out_kernel(float* __restrict__ out,
                                const float* __restrict__ cw,
                                const float* __restrict__ bias) {
    size_t idx = (size_t)blockIdx.x * blockDim.x + threadIdx.x;
    const size_t n4 = (size_t)M_DIM * N_DIM / 4;
    if (idx >= n4) return;
    size_t b = idx >> 8;
    int    o = (int)(idx & 255) * 4;
    float4 acc = make_float4(0.f, 0.f, 0.f, 0.f);
#pragma unroll
    for (int e = 0; e < E_DIM; ++e) {
        float c = cw[b * E_DIM + e];
        float4 bz = *reinterpret_cast<const float4*>(bias + (size_t)e * N_DIM + o);
        acc.x += c * bz.x; acc.y += c * bz.y;
        acc.z += c * bz.z; acc.w += c * bz.w;
    }
    *reinterpret_cast<float4*>(out + b * N_DIM + o) = acc;
}

__global__ void relu_kernel(float* __restrict__ out) {
    size_t idx    = (size_t)blockIdx.x * blockDim.x + threadIdx.x;
    size_t stride = (size_t)gridDim.x * blockDim.x;
    const size_t n4 = (size_t)M_DIM * N_DIM / 4;
    for (; idx < n4; idx += stride) {
        float4 v = reinterpret_cast<float4*>(out)[idx];
        v.x = fmaxf(v.x, 0.f); v.y = fmaxf(v.y, 0.f);
        v.z = fmaxf(v.z, 0.f); v.w = fmaxf(v.w, 0.f);
        reinterpret_cast<float4*>(out)[idx] = v;
    }
}

// ---------------- asm helpers ----------------
__device__ __forceinline__ void cp_async16(uint32_t s, const void* g) {
    asm volatile("cp.async.cg.shared.global [%0], [%1], 16;\n" :: "r"(s), "l"(g));
}
__device__ __forceinline__ void cpasync_arrive_noinc(uint32_t mbar) {
    asm volatile("cp.async.mbarrier.arrive.noinc.shared::cta.b64 [%0];" :: "r"(mbar) : "memory");
}
__device__ __forceinline__ void mbar_init(uint32_t a, uint32_t cnt) {
    asm volatile("mbarrier.init.shared.b64 [%0], %1;" :: "r"(a), "r"(cnt) : "memory");
}
__device__ __forceinline__ void mbar_arrive(uint32_t a) {
    asm volatile("mbarrier.arrive.shared.b64 _, [%0];" :: "r"(a) : "memory");
}
__device__ __forceinline__ void wait_parity(uint32_t mbar, uint32_t ph) {
    asm volatile("{\n\t.reg .pred P;\nWL%=:\n\t"
                 "mbarrier.try_wait.parity.acquire.cta.shared::cta.b64 P, [%0], %1, 0x989680;\n\t"
                 "@!P bra WL%=;\n\t}"
                 :: "r"(mbar), "r"(ph) : "memory");
}
__device__ __forceinline__ void ldsm_x4(uint32_t* r, uint32_t addr) {
    asm volatile("ldmatrix.sync.aligned.m8n8.x4.shared.b16 {%0,%1,%2,%3}, [%4];"
                 : "=r"(r[0]), "=r"(r[1]), "=r"(r[2]), "=r"(r[3]) : "r"(addr));
}
__device__ __forceinline__ uint32_t lds32(uint32_t addr) {
    uint32_t v;
    asm volatile("ld.shared.b32 %0, [%1];" : "=r"(v) : "r"(addr));
    return v;
}
__device__ __forceinline__ uint32_t mul_f16x2(uint32_t a, uint32_t s) {
    uint32_t d;
    asm("mul.rn.f16x2 %0, %1, %2;" : "=r"(d) : "r"(a), "r"(s));
    return d;
}
__device__ __forceinline__ void mma_f16(float* c, const uint32_t* a, const uint32_t* b) {
    asm volatile(
        "mma.sync.aligned.m16n8k16.row.col.f32.f16.f16.f32 "
        "{%0,%1,%2,%3}, {%4,%5,%6,%7}, {%8,%9}, {%0,%1,%2,%3};"
        : "+f"(c[0]), "+f"(c[1]), "+f"(c[2]), "+f"(c[3])
        : "r"(a[0]), "r"(a[1]), "r"(a[2]), "r"(a[3]), "r"(b[0]), "r"(b[1]));
}

// ---------------- tile loader ----------------
// Both smem tiles [128 rows][64 k] fp16, row = 128B = 8 chunks, swizzle ch ^ (row & 7)
__device__ __forceinline__ void issue_stage(uint32_t st,
                                            const __half* pA, const __half* pB,
                                            uint32_t dst0) {
#pragma unroll
    for (int p = 0; p < 4; ++p)
        cp_async16(st + A_OFF + dst0 + p * (32 * 128), pA + (size_t)p * 32 * I_DIM);
#pragma unroll
    for (int p = 0; p < 4; ++p)
        cp_async16(st + B_OFF + dst0 + p * (32 * 128), pB + (size_t)p * 32 * K_DIM);
}

// ---------------- fragment loads + in-register A scaling ----------------
// a regs from ldsm: r0=(rows0-7), r1=(rows8-15) @k0-7; r2,r3 same rows @k8-15.
// scale(r0,r2) = cw[row], scale(r1,r3) = cw[row+8]; table holds half2(s,s).
__device__ __forceinline__ void load_frags(uint32_t st, int s,
                                           int wm, int wn, int lane,
                                           uint32_t cwbase,
                                           uint32_t a[4][4], uint32_t b[4][2]) {
    const int r16 = lane & 15;
    const int hh  = lane >> 4;
    const int qr  = lane >> 2;          // scale row within 16-row tile
#pragma unroll
    for (int mt = 0; mt < 4; ++mt) {
        int row = wm * 64 + mt * 16 + r16;
        int ch  = s * 2 + hh;
        ldsm_x4(a[mt], st + A_OFF + (uint32_t)(row * 128 + ((ch ^ (row & 7)) << 4)));
        uint32_t saddr = cwbase + (uint32_t)((wm * 64 + mt * 16 + qr) << 2);
        uint32_t slo = lds32(saddr);
        uint32_t shi = lds32(saddr + 32);   // row + 8
        a[mt][0] = mul_f16x2(a[mt][0], slo);
        a[mt][2] = mul_f16x2(a[mt][2], slo);
        a[mt][1] = mul_f16x2(a[mt][1], shi);
        a[mt][3] = mul_f16x2(a[mt][3], shi);
    }
    const int m  = lane >> 3;
    const int rr = lane & 7;
    {
        int n  = wn * 32 + ((m >> 1) << 3) + rr;
        int ch = s * 2 + (m & 1);
        uint32_t t[4];
        ldsm_x4(t, st + B_OFF + (uint32_t)(n * 128 + ((ch ^ (n & 7)) << 4)));
        b[0][0] = t[0]; b[0][1] = t[1];
        b[1][0] = t[2]; b[1][1] = t[3];
        int n2 = n + 16;
        ldsm_x4(t, st + B_OFF + (uint32_t)(n2 * 128 + ((ch ^ (n2 & 7)) << 4)));
        b[2][0] = t[0]; b[2][1] = t[1];
        b[3][0] = t[2]; b[3][1] = t[3];
    }
}

// ---------------- main GEMM (split-K x8 over experts, frag-scaled A) ---------
__global__ void __launch_bounds__(NTHREADS, 2)
gemm_kernel(float* __restrict__ out, const float* __restrict__ cw) {
    extern __shared__ char smem_raw[];
    const uint32_t smem_base = (uint32_t)__cvta_generic_to_shared(smem_raw);
    const int tid  = threadIdx.x;
    const int lane = tid & 31;
    const int warp = tid >> 5;
    const int wm   = warp >> 2;   // 0..1
    const int wn   = warp & 3;    // 0..3
    const int bm0  = blockIdx.y * BM;
    const int bn0  = blockIdx.x * BN;
    const int z    = blockIdx.z;  // experts {2z, 2z+1}

    // cw scale table: cw_sm[ee][row] = half2(cw[bm0+row][2z+ee]) broadcast
    {
        int row = tid & 127, ee = tid >> 7;
        float v = cw[(size_t)(bm0 + row) * E_DIM + 2 * z + ee];
        __half h = __float2half_rn(v);
        __half2 h2; h2.x = h; h2.y = h;
        asm volatile("st.shared.b32 [%0], %1;"
                     :: "r"(smem_base + CW_OFF + (uint32_t)((ee * 128 + row) << 2)),
                        "r"(*reinterpret_cast<uint32_t*>(&h2)) : "memory");
    }
    if (tid == 0) {
#pragma unroll
        for (int s = 0; s < STAGES; ++s) {
            mbar_init(smem_base + FULL_OFF(s),  NTHREADS);
            mbar_init(smem_base + EMPTY_OFF(s), 8);
        }
    }
    __syncthreads();

    const int prow = tid >> 3, pch = tid & 7;
    const uint32_t dst0 = (uint32_t)(prow * 128 + ((pch ^ (prow & 7)) << 4));
    const __half* pAbase = g_X  + (size_t)(bm0 + prow) * I_DIM + pch * 8;
    const __half* pBbase = g_Wt + (size_t)(bn0 + prow) * K_DIM + (size_t)z * 2048 + pch * 8;

    float c[4][4][4];
#pragma unroll
    for (int i = 0; i < 4; ++i)
#pragma unroll
        for (int j = 0; j < 4; ++j)
#pragma unroll
            for (int k = 0; k < 4; ++k) c[i][j][k] = 0.f;

#pragma unroll
    for (int s = 0; s < STAGES - 1; ++s) {
        issue_stage(smem_base + s * STAGE_BYTES,
                    pAbase + ((s & 15) << 6), pBbase + (s << 6), dst0);
        cpasync_arrive_noinc(smem_base + FULL_OFF(s));
    }

    int prod_s = STAGES - 1; uint32_t prod_ph = 1;
    int cons_s = 0;          uint32_t cons_ph = 0;

    for (int kt = 0; kt < NT_ITERS; ++kt) {
        wait_parity(smem_base + FULL_OFF(cons_s), cons_ph);
        const uint32_t st = smem_base + cons_s * STAGE_BYTES;
        const uint32_t cwbase = smem_base + CW_OFF + (uint32_t)((kt >> 4) << 9);

        uint32_t a[4][4], b[4][2];
        load_frags(st, 0, wm, wn, lane, cwbase, a, b);

        const int ktp = kt + STAGES - 1;
        if (ktp < NT_ITERS) {
            wait_parity(smem_base + EMPTY_OFF(prod_s), prod_ph);
            issue_stage(smem_base + prod_s * STAGE_BYTES,
                        pAbase + ((ktp & 15) << 6), pBbase + (ktp << 6), dst0);
            cpasync_arrive_noinc(smem_base + FULL_OFF(prod_s));
            if (++prod_s == STAGES) { prod_s = 0; prod_ph ^= 1; }
        }

#pragma unroll
        for (int mt = 0; mt < 4; ++mt)
#pragma unroll
            for (int nt = 0; nt < 4; ++nt)
                mma_f16(c[mt][nt], a[mt], b[nt]);

#pragma unroll
        for (int s = 1; s < 4; ++s) {
            load_frags(st, s, wm, wn, lane, cwbase, a, b);
#pragma unroll
            for (int mt = 0; mt < 4; ++mt)
#pragma unroll
                for (int nt = 0; nt < 4; ++nt)
                    mma_f16(c[mt][nt], a[mt], b[nt]);
        }

        if (lane == 0) mbar_arrive(smem_base + EMPTY_OFF(cons_s));
        if (++cons_s == STAGES) { cons_s = 0; cons_ph ^= 1; }
    }

    // epilogue: atomic accumulate (scales already applied; bias in init_out)
    const int gr = lane >> 2;
    const int ct = lane & 3;
#pragma unroll
    for (int mt = 0; mt < 4; ++mt) {
#pragma unroll
        for (int nt = 0; nt < 4; ++nt) {
            int row = bm0 + wm * 64 + mt * 16 + gr;
            int o   = bn0 + wn * 32 + nt * 8 + ct * 2;
            float* p0 = out + (size_t)row * N_DIM + o;
            atomicAdd(p0,     c[mt][nt][0]);
            atomicAdd(p0 + 1, c[mt][nt][1]);
            float* p1 = p0 + (size_t)8 * N_DIM;
            atomicAdd(p1,     c[mt][nt][2]);
            atomicAdd(p1 + 1, c[mt][nt][3]);
        }
    }
}

// ---------------- launch -----------------------------------------------------
extern "C" void kernel_launch(void* const* d_in, const int* in_sizes, int n_in,
                              void* d_out, int out_size) {
    const float* x = nullptr;
    const float* cw = nullptr;
    const float* W = nullptr;
    const float* bias = nullptr;
    for (int i = 0; i < n_in; ++i) {
        switch (in_sizes[i]) {
            case M_DIM * I_DIM:         x    = (const float*)d_in[i]; break;
            case M_DIM * E_DIM:         cw   = (const float*)d_in[i]; break;
            case E_DIM * I_DIM * N_DIM: W    = (const float*)d_in[i]; break;
            case E_DIM * N_DIM:         bias = (const float*)d_in[i]; break;
            default: break;
        }
    }
    float* out = (float*)d_out;

    init_out_kernel<<<(M_DIM * N_DIM / 4 + 255) / 256, 256>>>(out, cw, bias);
    prep_x_kernel<<<1024, 256>>>(x);
    prep_w_kernel<<<dim3(K_DIM / 32, N_DIM / 32), dim3(32, 8)>>>(W);

    cudaFuncSetAttribute(gemm_kernel, cudaFuncAttributeMaxDynamicSharedMemorySize,
                         SMEM_TOTAL);
    dim3 grid(N_DIM / BN, M_DIM / BM, KCHUNKS);  // (8, 32, 8) = 2048 CTAs
    gemm_kernel<<<grid, NTHREADS, SMEM_TOTAL>>>(out, cw);

    relu_kernel<<<1024, 256>>>(out);
}

// round 15
// speedup vs baseline: 1.1038x; 1.1038x over previous
#include <cuda_runtime.h>
#include <cuda_fp16.h>
#include <cstdint>

// ---------------- problem dims ----------------
#define M_DIM 4096
#define N_DIM 1024
#define E_DIM 16
#define I_DIM 1024
#define K_DIM 16384
#define KS    16448          // K extended by one BK tile carrying cw/bias rank-16 term

// ---------------- GEMM config -----------------
#define BM 128
#define BN 128
#define BK 64
#define STAGES 3
#define NTHREADS 256
#define KCHUNKS 8            // split-K: 2048 CTAs -> 6.92 per occ-2 slot -> 98.8% balance

// smem: 3 stages of (A 16KB + B 16KB), then mbarriers
#define A_OFF 0
#define B_OFF 16384
#define STAGE_BYTES 32768
#define BAR_BASE (STAGES * STAGE_BYTES)
#define FULL_OFF(s)  (BAR_BASE + (s) * 8)
#define EMPTY_OFF(s) (BAR_BASE + 24 + (s) * 8)
#define SMEM_TOTAL (BAR_BASE + 64)               // 98368 -> 2 CTAs/SM

// ---------------- device scratch --------------
__device__ __align__(1024) __half g_A [(size_t)M_DIM * KS];  // ~128.5 MiB: [cw*x | cw | 0]
__device__ __align__(1024) __half g_Wt[(size_t)N_DIM * KS];  // ~32.1 MiB:  W^T [n][k] + bias tail

// ---------------- prep kernels (R12, unchanged) ----------------
__global__ void prep_w_kernel(const float* __restrict__ W) {
    __shared__ float t[32][33];
    const int k0 = blockIdx.x * 32, o0 = blockIdx.y * 32;
    const int tx = threadIdx.x, ty = threadIdx.y;  // 32 x 8
#pragma unroll
    for (int i = 0; i < 4; ++i)
        t[ty + i * 8][tx] = W[(size_t)(k0 + ty + i * 8) * N_DIM + o0 + tx];
    __syncthreads();
#pragma unroll
    for (int i = 0; i < 4; ++i) {
        float v = t[tx][ty + i * 8];
        g_Wt[(size_t)(o0 + ty + i * 8) * KS + k0 + tx] = __float2half_rn(v);
    }
}

__global__ void prep_a_kernel(const float* __restrict__ x,
                              const float* __restrict__ cw) {
    size_t idx    = (size_t)blockIdx.x * blockDim.x + threadIdx.x;
    size_t stride = (size_t)gridDim.x * blockDim.x;
    const size_t total = (size_t)M_DIM * (I_DIM / 4);
    for (; idx < total; idx += stride) {
        size_t b  = idx >> 8;
        int    i4 = (int)(idx & 255) * 4;
        float4 xv = *reinterpret_cast<const float4*>(x + (b << 10) + i4);
        const float4 c0 = *reinterpret_cast<const float4*>(cw + b * E_DIM);
        const float4 c1 = *reinterpret_cast<const float4*>(cw + b * E_DIM + 4);
        const float4 c2 = *reinterpret_cast<const float4*>(cw + b * E_DIM + 8);
        const float4 c3 = *reinterpret_cast<const float4*>(cw + b * E_DIM + 12);
        float cs[16] = {c0.x, c0.y, c0.z, c0.w, c1.x, c1.y, c1.z, c1.w,
                        c2.x, c2.y, c2.z, c2.w, c3.x, c3.y, c3.z, c3.w};
        __half* dst = g_A + b * KS + i4;
#pragma unroll
        for (int e = 0; e < E_DIM; ++e) {
            float c = cs[e];
            __half2 h0 = __floats2half2_rn(c * xv.x, c * xv.y);
            __half2 h1 = __floats2half2_rn(c * xv.z, c * xv.w);
            uint2 o;
            o.x = *reinterpret_cast<uint32_t*>(&h0);
            o.y = *reinterpret_cast<uint32_t*>(&h1);
            *reinterpret_cast<uint2*>(dst + e * I_DIM) = o;
        }
    }
}

__global__ void prep_tail_kernel(const float* __restrict__ cw,
                                 const float* __restrict__ bias) {
    int idx = blockIdx.x * blockDim.x + threadIdx.x;
    if (idx < M_DIM * 64) {
        int b = idx >> 6, e = idx & 63;
        g_A[(size_t)b * KS + K_DIM + e] =
            (e < E_DIM) ? __float2half_rn(cw[b * E_DIM + e]) : __half(0.f);
    } else {
        int j = idx - M_DIM * 64;
        if (j < 64 * N_DIM) {
            int e = j >> 10, o = j & 1023;
            g_Wt[(size_t)o * KS + K_DIM + e] =
                (e < E_DIM) ? __float2half_rn(bias[e * N_DIM + o]) : __half(0.f);
        }
    }
}

// ---------------- out zero / relu ----------------
__global__ void zero_out_kernel(float* __restrict__ out) {
    size_t idx    = (size_t)blockIdx.x * blockDim.x + threadIdx.x;
    size_t stride = (size_t)gridDim.x * blockDim.x;
    const size_t n4 = (size_t)M_DIM * N_DIM / 4;
    float4 z = make_float4(0.f, 0.f, 0.f, 0.f);
    for (; idx < n4; idx += stride)
        reinterpret_cast<float4*>(out)[idx] = z;
}

__global__ void relu_kernel(float* __restrict__ out) {
    size_t idx    = (size_t)blockIdx.x * blockDim.x + threadIdx.x;
    size_t stride = (size_t)gridDim.x * blockDim.x;
    const size_t n4 = (size_t)M_DIM * N_DIM / 4;
    for (; idx < n4; idx += stride) {
        float4 v = reinterpret_cast<float4*>(out)[idx];
        v.x = fmaxf(v.x, 0.f); v.y = fmaxf(v.y, 0.f);
        v.z = fmaxf(v.z, 0.f); v.w = fmaxf(v.w, 0.f);
        reinterpret_cast<float4*>(out)[idx] = v;
    }
}

// ---------------- asm helpers ----------------
__device__ __forceinline__ void cp_async16(uint32_t s, const void* g) {
    asm volatile("cp.async.cg.shared.global [%0], [%1], 16;\n" :: "r"(s), "l"(g));
}
__device__ __forceinline__ void cpasync_arrive_noinc(uint32_t mbar) {
    asm volatile("cp.async.mbarrier.arrive.noinc.shared::cta.b64 [%0];" :: "r"(mbar) : "memory");
}
__device__ __forceinline__ void mbar_init(uint32_t a, uint32_t cnt) {
    asm volatile("mbarrier.init.shared.b64 [%0], %1;" :: "r"(a), "r"(cnt) : "memory");
}
__device__ __forceinline__ void mbar_arrive(uint32_t a) {
    asm volatile("mbarrier.arrive.shared.b64 _, [%0];" :: "r"(a) : "memory");
}
__device__ __forceinline__ void wait_parity(uint32_t mbar, uint32_t ph) {
    asm volatile("{\n\t.reg .pred P;\nWL%=:\n\t"
                 "mbarrier.try_wait.parity.acquire.cta.shared::cta.b64 P, [%0], %1, 0x989680;\n\t"
                 "@!P bra WL%=;\n\t}"
                 :: "r"(mbar), "r"(ph) : "memory");
}
__device__ __forceinline__ void ldsm_x4(uint32_t* r, uint32_t addr) {
    asm volatile("ldmatrix.sync.aligned.m8n8.x4.shared.b16 {%0,%1,%2,%3}, [%4];"
                 : "=r"(r[0]), "=r"(r[1]), "=r"(r[2]), "=r"(r[3]) : "r"(addr));
}
__device__ __forceinline__ void mma_f16(float* c, const uint32_t* a, const uint32_t* b) {
    asm volatile(
        "mma.sync.aligned.m16n8k16.row.col.f32.f16.f16.f32 "
        "{%0,%1,%2,%3}, {%4,%5,%6,%7}, {%8,%9}, {%0,%1,%2,%3};"
        : "+f"(c[0]), "+f"(c[1]), "+f"(c[2]), "+f"(c[3])
        : "r"(a[0]), "r"(a[1]), "r"(a[2]), "r"(a[3]), "r"(b[0]), "r"(b[1]));
}
// vectorized no-return reduction: out[0] += a, out[1] += b
__device__ __forceinline__ void red_add_v2(float* p, float a, float b) {
    asm volatile("red.global.add.v2.f32 [%0], {%1, %2};"
                 :: "l"(p), "f"(a), "f"(b) : "memory");
}

// ---------------- tile loader ----------------
__device__ __forceinline__ void issue_stage(uint32_t st,
                                            const __half* pA, const __half* pB,
                                            uint32_t dst0) {
#pragma unroll
    for (int p = 0; p < 4; ++p)
        cp_async16(st + A_OFF + dst0 + p * (32 * 128), pA + (size_t)p * 32 * KS);
#pragma unroll
    for (int p = 0; p < 4; ++p)
        cp_async16(st + B_OFF + dst0 + p * (32 * 128), pB + (size_t)p * 32 * KS);
}

// ---------------- fragment loads (verified mapping) ----------------
__device__ __forceinline__ void load_frags(uint32_t st, int s,
                                           int wm, int wn, int lane,
                                           uint32_t a[4][4], uint32_t b[4][2]) {
    const int r16 = lane & 15;
    const int hh  = lane >> 4;
#pragma unroll
    for (int mt = 0; mt < 4; ++mt) {
        int row = wm * 64 + mt * 16 + r16;
        int ch  = s * 2 + hh;
        ldsm_x4(a[mt], st + A_OFF + (uint32_t)(row * 128 + ((ch ^ (row & 7)) << 4)));
    }
    const int m  = lane >> 3;
    const int rr = lane & 7;
    {
        int n  = wn * 32 + ((m >> 1) << 3) + rr;
        int ch = s * 2 + (m & 1);
        uint32_t t[4];
        ldsm_x4(t, st + B_OFF + (uint32_t)(n * 128 + ((ch ^ (n & 7)) << 4)));
        b[0][0] = t[0]; b[0][1] = t[1];
        b[1][0] = t[2]; b[1][1] = t[3];
        int n2 = n + 16;
        ldsm_x4(t, st + B_OFF + (uint32_t)(n2 * 128 + ((ch ^ (n2 & 7)) << 4)));
        b[2][0] = t[0]; b[2][1] = t[1];
        b[3][0] = t[2]; b[3][1] = t[3];
    }
}

// ---------------- main GEMM (R12 core + vector-red epilogue) -----------------
__global__ void __launch_bounds__(NTHREADS, 2)
gemm_kernel(float* __restrict__ out) {
    extern __shared__ char smem_raw[];
    const uint32_t smem_base = (uint32_t)__cvta_generic_to_shared(smem_raw);
    const int tid  = threadIdx.x;
    const int lane = tid & 31;
    const int warp = tid >> 5;
    const int wm   = warp >> 2;   // 0..1
    const int wn   = warp & 3;    // 0..3
    const int bm0  = blockIdx.y * BM;
    const int bn0  = blockIdx.x * BN;
    const int kz   = blockIdx.z;
    const int kt0  = kz * 32;
    const int NT   = (kz == KCHUNKS - 1) ? (KS / BK - kt0) : 32;  // 32 or 33

    if (tid == 0) {
#pragma unroll
        for (int s = 0; s < STAGES; ++s) {
            mbar_init(smem_base + FULL_OFF(s),  NTHREADS);
            mbar_init(smem_base + EMPTY_OFF(s), 8);
        }
    }
    __syncthreads();

    const int prow = tid >> 3, pch = tid & 7;
    const uint32_t dst0 = (uint32_t)(prow * 128 + ((pch ^ (prow & 7)) << 4));
    const __half* pA = g_A  + (size_t)(bm0 + prow) * KS + pch * 8 + (size_t)kt0 * BK;
    const __half* pB = g_Wt + (size_t)(bn0 + prow) * KS + pch * 8 + (size_t)kt0 * BK;

    float c[4][4][4];
#pragma unroll
    for (int i = 0; i < 4; ++i)
#pragma unroll
        for (int j = 0; j < 4; ++j)
#pragma unroll
            for (int k = 0; k < 4; ++k) c[i][j][k] = 0.f;

#pragma unroll
    for (int s = 0; s < STAGES - 1; ++s) {
        issue_stage(smem_base + s * STAGE_BYTES, pA, pB, dst0);
        cpasync_arrive_noinc(smem_base + FULL_OFF(s));
        pA += BK; pB += BK;
    }

    int prod_s = STAGES - 1; uint32_t prod_ph = 1;
    int cons_s = 0;          uint32_t cons_ph = 0;

    for (int kt = 0; kt < NT; ++kt) {
        wait_parity(smem_base + FULL_OFF(cons_s), cons_ph);
        const uint32_t st = smem_base + cons_s * STAGE_BYTES;

        uint32_t a[4][4], b[4][2];
        load_frags(st, 0, wm, wn, lane, a, b);

        if (kt + STAGES - 1 < NT) {
            wait_parity(smem_base + EMPTY_OFF(prod_s), prod_ph);
            issue_stage(smem_base + prod_s * STAGE_BYTES, pA, pB, dst0);
            cpasync_arrive_noinc(smem_base + FULL_OFF(prod_s));
            pA += BK; pB += BK;
            if (++prod_s == STAGES) { prod_s = 0; prod_ph ^= 1; }
        }

#pragma unroll
        for (int mt = 0; mt < 4; ++mt)
#pragma unroll
            for (int nt = 0; nt < 4; ++nt)
                mma_f16(c[mt][nt], a[mt], b[nt]);

#pragma unroll
        for (int s = 1; s < 4; ++s) {
            load_frags(st, s, wm, wn, lane, a, b);
#pragma unroll
            for (int mt = 0; mt < 4; ++mt)
#pragma unroll
                for (int nt = 0; nt < 4; ++nt)
                    mma_f16(c[mt][nt], a[mt], b[nt]);
        }

        if (lane == 0) mbar_arrive(smem_base + EMPTY_OFF(cons_s));
        if (++cons_s == STAGES) { cons_s = 0; cons_ph ^= 1; }
    }

    // epilogue: vectorized no-return reductions (ReLU deferred)
    const int gr = lane >> 2;
    const int ct = lane & 3;
#pragma unroll
    for (int mt = 0; mt < 4; ++mt) {
#pragma unroll
        for (int nt = 0; nt < 4; ++nt) {
            int row = bm0 + wm * 64 + mt * 16 + gr;
            int o   = bn0 + wn * 32 + nt * 8 + ct * 2;
            float* p0 = out + (size_t)row * N_DIM + o;
            red_add_v2(p0, c[mt][nt][0], c[mt][nt][1]);
            red_add_v2(p0 + (size_t)8 * N_DIM, c[mt][nt][2], c[mt][nt][3]);
        }
    }
}

// ---------------- launch -----------------------------------------------------
extern "C" void kernel_launch(void* const* d_in, const int* in_sizes, int n_in,
                              void* d_out, int out_size) {
    const float* x = nullptr;
    const float* cw = nullptr;
    const float* W = nullptr;
    const float* bias = nullptr;
    for (int i = 0; i < n_in; ++i) {
        switch (in_sizes[i]) {
            case M_DIM * I_DIM:         x    = (const float*)d_in[i]; break;
            case M_DIM * E_DIM:         cw   = (const float*)d_in[i]; break;
            case E_DIM * I_DIM * N_DIM: W    = (const float*)d_in[i]; break;
            case E_DIM * N_DIM:         bias = (const float*)d_in[i]; break;
            default: break;
        }
    }
    float* out = (float*)d_out;

    zero_out_kernel<<<1024, 256>>>(out);
    prep_w_kernel<<<dim3(K_DIM / 32, N_DIM / 32), dim3(32, 8)>>>(W);
    prep_a_kernel<<<4096, 256>>>(x, cw);
    prep_tail_kernel<<<(M_DIM * 64 + 64 * N_DIM + 255) / 256, 256>>>(cw, bias);

    cudaFuncSetAttribute(gemm_kernel, cudaFuncAttributeMaxDynamicSharedMemorySize,
                         SMEM_TOTAL);
    dim3 grid(N_DIM / BN, M_DIM / BM, KCHUNKS);  // (8, 32, 8) = 2048 CTAs
    gemm_kernel<<<grid, NTHREADS, SMEM_TOTAL>>>(out);

    relu_kernel<<<1024, 256>>>(out);
}